// round 8
// baseline (speedup 1.0000x reference)
#include <cuda_runtime.h>
#include <cuda_fp16.h>
#include <cstdint>

typedef unsigned int u32;

#define Bn 4
#define Ln 2048
#define Sn 2048
#define Hn 16
#define En 64
#define Dn 64
#define BM 64
#define BN 64
#define NT 256
#define NTILES (Sn / BN)
#define L2E 1.44269504f
#define ONE2 0x3C003C00u

// pitch: 64 elems * 2B + 16B pad = 144 bytes (conflict-free ldmatrix)
#define PITCH 144
#define QTB (64 * PITCH)      // 9216 (Q tile: 64 rows)
#define KTB (64 * PITCH)      // 9216 (K/V tile: 64 rows)
#define OFF_QH 0
#define OFF_QL (OFF_QH + QTB)
#define OFF_KV(buf) (2 * QTB + (buf) * 2 * KTB)
#define SMEM_BYTES (2 * QTB + 2 * 2 * KTB)   // 55296
// combine region overlays the KV buffers after the main loop
#define OFF_CMB OFF_KV(0)
#define OBS 68                 // obuf row stride (floats), bank-spread

// ---------------- scratch (fp16, repacked [b,h,s,e]) ----------------
__device__ __half g_Qh[(size_t)Bn * Hn * Ln * En];
__device__ __half g_Ql[(size_t)Bn * Hn * Ln * En];
__device__ __half g_Kf[(size_t)Bn * Hn * Sn * En];
__device__ __half g_Vf[(size_t)Bn * Hn * Sn * Dn];

// ---------------- helpers ----------------
__device__ __forceinline__ u32 smem_u32(const void* p) {
    u32 a;
    asm("{ .reg .u64 t; cvta.to.shared.u64 t, %1; cvt.u32.u64 %0, t; }" : "=r"(a) : "l"(p));
    return a;
}
__device__ __forceinline__ void cpa16(u32 dst, const void* src) {
    asm volatile("cp.async.cg.shared.global [%0], [%1], 16;" :: "r"(dst), "l"(src));
}
__device__ __forceinline__ void cpa_commit() {
    asm volatile("cp.async.commit_group;" ::: "memory");
}
template <int N>
__device__ __forceinline__ void cpa_wait() {
    asm volatile("cp.async.wait_group %0;" :: "n"(N) : "memory");
}
__device__ __forceinline__ void ldsm_x4(u32* r, u32 addr) {
    asm volatile("ldmatrix.sync.aligned.m8n8.x4.shared.b16 {%0,%1,%2,%3}, [%4];"
                 : "=r"(r[0]), "=r"(r[1]), "=r"(r[2]), "=r"(r[3]) : "r"(addr));
}
__device__ __forceinline__ void ldsm_x4_t(u32* r, u32 addr) {
    asm volatile("ldmatrix.sync.aligned.m8n8.x4.trans.shared.b16 {%0,%1,%2,%3}, [%4];"
                 : "=r"(r[0]), "=r"(r[1]), "=r"(r[2]), "=r"(r[3]) : "r"(addr));
}
__device__ __forceinline__ void mma_fp16(float* c, const u32* a, u32 b0, u32 b1) {
    asm volatile(
        "mma.sync.aligned.m16n8k16.row.col.f32.f16.f16.f32 "
        "{%0,%1,%2,%3}, {%4,%5,%6,%7}, {%8,%9}, {%0,%1,%2,%3};"
        : "+f"(c[0]), "+f"(c[1]), "+f"(c[2]), "+f"(c[3])
        : "r"(a[0]), "r"(a[1]), "r"(a[2]), "r"(a[3]), "r"(b0), "r"(b1));
}
__device__ __forceinline__ u32 cvt_f16x2(float lo, float hi) {
    u32 d;
    asm("cvt.rn.f16x2.f32 %0, %1, %2;" : "=r"(d) : "f"(hi), "f"(lo));
    return d;
}
__device__ __forceinline__ u32 ex2_f16x2(u32 x) {
    u32 d;
    asm("ex2.approx.f16x2 %0, %1;" : "=r"(d) : "r"(x));
    return d;
}

// ---------------- fused pre-pass ----------------
__global__ void pack_all(const float* __restrict__ Q, const float* __restrict__ K,
                         const float* __restrict__ V) {
    const int region = blockIdx.y;
    const int i4 = blockIdx.x * 256 + threadIdx.x;
    const size_t lin = (size_t)i4 * 4;
    const int e = lin & 63;
    const int h = (lin >> 6) & 15;
    const int x = (lin >> 10) & 2047;
    const int b = (int)(lin >> 21);
    const size_t dst = ((((size_t)b * Hn + h) * Ln + x) * En) + e;

    if (region == 0) {
        float4 v = ((const float4*)Q)[i4];
        float xx[4] = {v.x, v.y, v.z, v.w};
        __half hh[4], ll[4];
#pragma unroll
        for (int j = 0; j < 4; ++j) {
            hh[j] = __float2half_rn(xx[j]);
            ll[j] = __float2half_rn(xx[j] - __half2float(hh[j]));
        }
        *(uint2*)(g_Qh + dst) = *(uint2*)hh;
        *(uint2*)(g_Ql + dst) = *(uint2*)ll;
    } else {
        const float* src = (region == 1) ? K : V;
        __half* out = (region == 1) ? g_Kf : g_Vf;
        float4 v = ((const float4*)src)[i4];
        __half hh[4] = {__float2half_rn(v.x), __float2half_rn(v.y),
                        __float2half_rn(v.z), __float2half_rn(v.w)};
        *(uint2*)(out + dst) = *(uint2*)hh;
    }
}

// ---------------- main attention kernel ----------------
extern __shared__ char dsm[];

__global__ __launch_bounds__(NT, 2)
void fattn_mma(float* __restrict__ O) {
    const u32 sb = smem_u32(dsm);
    const int tid = threadIdx.x;
    const int w = tid >> 5;
    const int lane = tid & 31;
    const int r = w >> 1;         // row-group (0..3): rows r*16..r*16+15
    const int g = w & 1;          // column half (0/1): s-cols g*32..g*32+31

    const int bh = blockIdx.y;
    const int b = bh >> 4, h = bh & 15;
    const int mbase = blockIdx.x * BM;

    const __half* gq_h = g_Qh + ((size_t)bh * Ln + mbase) * En;
    const __half* gq_l = g_Ql + ((size_t)bh * Ln + mbase) * En;
    const __half* gk   = g_Kf + (size_t)bh * Sn * En;
    const __half* gv   = g_Vf + (size_t)bh * Sn * Dn;

    // prologue: Q (64 rows hi/lo) + tile0 K,V  (512 uint4 per array)
#pragma unroll
    for (int i = 0; i < 2; ++i) {
        int idx = tid + i * NT;
        u32 d = sb + (idx >> 3) * PITCH + (idx & 7) * 16;
        cpa16(d + OFF_QH, (const char*)gq_h + idx * 16);
        cpa16(d + OFF_QL, (const char*)gq_l + idx * 16);
        u32 dk = sb + OFF_KV(0) + (idx >> 3) * PITCH + (idx & 7) * 16;
        cpa16(dk + 0 * KTB, (const char*)gk + idx * 16);
        cpa16(dk + 1 * KTB, (const char*)gv + idx * 16);
    }
    cpa_commit();

    const u32 koff = (lane & 7) * PITCH + (lane >> 3) * 16;
    const u32 qoff = (16 * r + ((lane >> 3) & 1) * 8 + (lane & 7)) * PITCH + (lane >> 4) * 16;
    const u32 voff = (((lane >> 3) & 1) * 8 + (lane & 7)) * PITCH + (lane >> 4) * 16;
    const u32 gsk = g * (32 * PITCH);

    u32 Qh[4][4], Ql[4][4];
    float accO[8][4];
#pragma unroll
    for (int j = 0; j < 8; ++j)
#pragma unroll
        for (int i = 0; i < 4; ++i) accO[j][i] = 0.f;
    float accL[4] = {0.f, 0.f, 0.f, 0.f};
    float m0 = -1e30f, m1 = -1e30f;   // per-warp running maxima

    for (int t = 0; t < NTILES; ++t) {
        const u32 kvb = sb + OFF_KV(t & 1);

        cpa_wait<0>();
        __syncthreads();

        if (t + 1 < NTILES) {
            const u32 nb = sb + OFF_KV((t + 1) & 1);
            const size_t goffK = (size_t)(t + 1) * BN * En;
            const size_t goffV = (size_t)(t + 1) * BN * Dn;
#pragma unroll
            for (int i = 0; i < 2; ++i) {
                int idx = tid + i * NT;
                u32 d = nb + (idx >> 3) * PITCH + (idx & 7) * 16;
                cpa16(d + 0 * KTB, (const char*)(gk + goffK) + idx * 16);
                cpa16(d + 1 * KTB, (const char*)(gv + goffV) + idx * 16);
            }
            cpa_commit();
        }

        if (t == 0) {
#pragma unroll
            for (int k = 0; k < 4; ++k) {
                ldsm_x4(Qh[k], sb + OFF_QH + k * 32 + qoff);
                ldsm_x4(Ql[k], sb + OFF_QL + k * 32 + qoff);
            }
        }

        // ---- S = Qh*K + Ql*K over this warp's 32 s-cols (pipelined) ----
        float accS[4][4];
#pragma unroll
        for (int j = 0; j < 4; ++j)
#pragma unroll
            for (int i = 0; i < 4; ++i) accS[j][i] = 0.f;

        {
            const u32 kbase = kvb + koff + gsk;
            u32 kc[4], kn[4];
            ldsm_x4(kc, kbase);
#pragma unroll
            for (int idx = 0; idx < 8; ++idx) {
                const int hh = idx >> 2, j = idx & 3;
                if (idx < 7) {
                    const int n = idx + 1;
                    ldsm_x4(kn, kbase + (n & 3) * (8 * PITCH) + (n >> 2) * 64);
                }
                mma_fp16(accS[j], Qh[2 * hh],     kc[0], kc[1]);
                mma_fp16(accS[j], Ql[2 * hh],     kc[0], kc[1]);
                mma_fp16(accS[j], Qh[2 * hh + 1], kc[2], kc[3]);
                mma_fp16(accS[j], Ql[2 * hh + 1], kc[2], kc[3]);
                kc[0] = kn[0]; kc[1] = kn[1]; kc[2] = kn[2]; kc[3] = kn[3];
            }
        }

        // ---- per-warp online softmax over its 32 cols ----
        float tm0 = accS[0][0], tm1 = accS[0][2];
#pragma unroll
        for (int j = 0; j < 4; ++j) {
            tm0 = fmaxf(tm0, fmaxf(accS[j][0], accS[j][1]));
            tm1 = fmaxf(tm1, fmaxf(accS[j][2], accS[j][3]));
        }
        tm0 = fmaxf(tm0, __shfl_xor_sync(0xffffffffu, tm0, 1));
        tm1 = fmaxf(tm1, __shfl_xor_sync(0xffffffffu, tm1, 1));
        tm0 = fmaxf(tm0, __shfl_xor_sync(0xffffffffu, tm0, 2));
        tm1 = fmaxf(tm1, __shfl_xor_sync(0xffffffffu, tm1, 2));

        const u32 vbase = kvb + 1 * KTB + voff + gsk;
        u32 vc[4], vn[4];
        ldsm_x4_t(vc, vbase);    // overlaps the ALU below

        const float nm0 = fmaxf(m0, tm0);
        const float nm1 = fmaxf(m1, tm1);
        const float al0 = __expf(m0 - nm0);
        const float al1 = __expf(m1 - nm1);
        m0 = nm0; m1 = nm1;
        const float c0 = -nm0 * L2E;
        const float c1 = -nm1 * L2E;

#pragma unroll
        for (int j = 0; j < 8; ++j) {
            accO[j][0] *= al0; accO[j][1] *= al0;
            accO[j][2] *= al1; accO[j][3] *= al1;
        }
        accL[0] *= al0;
        accL[2] *= al1;

        // ---- PV over this warp's 32 s-rows of V (pipelined) ----
#pragma unroll
        for (int idx = 0; idx < 8; ++idx) {
            const int kt = idx >> 2, q = idx & 3;
            u32 ah[4];
            if (q == 0) {
                ah[0] = ex2_f16x2(cvt_f16x2(fmaf(accS[2 * kt][0], L2E, c0),
                                            fmaf(accS[2 * kt][1], L2E, c0)));
                ah[1] = ex2_f16x2(cvt_f16x2(fmaf(accS[2 * kt][2], L2E, c1),
                                            fmaf(accS[2 * kt][3], L2E, c1)));
                ah[2] = ex2_f16x2(cvt_f16x2(fmaf(accS[2 * kt + 1][0], L2E, c0),
                                            fmaf(accS[2 * kt + 1][1], L2E, c0)));
                ah[3] = ex2_f16x2(cvt_f16x2(fmaf(accS[2 * kt + 1][2], L2E, c1),
                                            fmaf(accS[2 * kt + 1][3], L2E, c1)));
                accS[2 * kt][0] = __uint_as_float(ah[0]);
                accS[2 * kt][1] = __uint_as_float(ah[1]);
                accS[2 * kt][2] = __uint_as_float(ah[2]);
                accS[2 * kt][3] = __uint_as_float(ah[3]);
                mma_fp16(accL, ah, ONE2, ONE2);
            } else {
                ah[0] = __float_as_uint(accS[2 * kt][0]);
                ah[1] = __float_as_uint(accS[2 * kt][1]);
                ah[2] = __float_as_uint(accS[2 * kt][2]);
                ah[3] = __float_as_uint(accS[2 * kt][3]);
            }
            if (idx < 7) {
                const int n = idx + 1;
                ldsm_x4_t(vn, vbase + (n >> 2) * (16 * PITCH) + (n & 3) * 32);
            }
            mma_fp16(accO[2 * q],     ah, vc[0], vc[1]);
            mma_fp16(accO[2 * q + 1], ah, vc[2], vc[3]);
            vc[0] = vn[0]; vc[1] = vn[1]; vc[2] = vn[2]; vc[3] = vn[3];
        }
    }

    // ---- cross-warp-pair combine (exact fp32, once) ----
    __syncthreads();   // all KV-buffer use done; reuse as combine scratch
    float* sm_m = (float*)(dsm + OFF_CMB);          // [8][16]
    float* sm_l = sm_m + 128;                       // [8][16]
    float* obuf = sm_l + 128;                       // [4][16][OBS]

    const int r0 = lane >> 2;
    if ((lane & 3) == 0) {
        sm_m[w * 16 + r0]     = m0;  sm_l[w * 16 + r0]     = accL[0];
        sm_m[w * 16 + r0 + 8] = m1;  sm_l[w * 16 + r0 + 8] = accL[2];
    }
    __syncthreads();
    const int wp = w ^ 1;
    const float mo0 = sm_m[wp * 16 + r0],     lo0 = sm_l[wp * 16 + r0];
    const float mo1 = sm_m[wp * 16 + r0 + 8], lo1 = sm_l[wp * 16 + r0 + 8];
    const float M0 = fmaxf(m0, mo0), M1 = fmaxf(m1, mo1);
    const float ss0 = __expf(m0 - M0), so0 = __expf(mo0 - M0);
    const float ss1 = __expf(m1 - M1), so1 = __expf(mo1 - M1);
    const float inv0 = 1.f / (accL[0] * ss0 + lo0 * so0);
    const float inv1 = 1.f / (accL[2] * ss1 + lo1 * so1);

    const int colb = 2 * (lane & 3);
    if (g == 1) {
#pragma unroll
        for (int j = 0; j < 8; ++j) {
            float* p0 = obuf + (r * 16 + r0) * OBS + j * 8 + colb;
            float* p1 = obuf + (r * 16 + r0 + 8) * OBS + j * 8 + colb;
            p0[0] = accO[j][0] * ss0;  p0[1] = accO[j][1] * ss0;
            p1[0] = accO[j][2] * ss1;  p1[1] = accO[j][3] * ss1;
        }
    }
    __syncthreads();
    if (g == 0) {
        const int row0 = mbase + r * 16 + r0;
        float* o0 = O + (((size_t)b * Ln + row0) * Hn + h) * Dn + colb;
        float* o1 = o0 + (size_t)8 * Hn * Dn;
#pragma unroll
        for (int j = 0; j < 8; ++j) {
            const float* p0 = obuf + (r * 16 + r0) * OBS + j * 8 + colb;
            const float* p1 = obuf + (r * 16 + r0 + 8) * OBS + j * 8 + colb;
            *(float2*)(o0 + 8 * j) = make_float2((accO[j][0] * ss0 + p0[0]) * inv0,
                                                 (accO[j][1] * ss0 + p0[1]) * inv0);
            *(float2*)(o1 + 8 * j) = make_float2((accO[j][2] * ss1 + p1[0]) * inv1,
                                                 (accO[j][3] * ss1 + p1[1]) * inv1);
        }
    }
}

// ---------------- launch ----------------
extern "C" void kernel_launch(void* const* d_in, const int* in_sizes, int n_in,
                              void* d_out, int out_size) {
    const float* Q = (const float*)d_in[0];
    const float* K = (const float*)d_in[1];
    const float* V = (const float*)d_in[2];
    float* O = (float*)d_out;

    pack_all<<<dim3(8192, 3), 256>>>(Q, K, V);

    cudaFuncSetAttribute(fattn_mma, cudaFuncAttributeMaxDynamicSharedMemorySize, SMEM_BYTES);
    fattn_mma<<<dim3(Ln / BM, Bn * Hn), NT, SMEM_BYTES>>>(O);
}

// round 10
// speedup vs baseline: 1.1494x; 1.1494x over previous
#include <cuda_runtime.h>
#include <cuda_fp16.h>
#include <cstdint>

typedef unsigned int u32;

#define Bn 4
#define Ln 2048
#define Sn 2048
#define Hn 16
#define En 64
#define Dn 64
#define BM 128
#define BN 64
#define NT 256
#define NTILES (Sn / BN)
#define L2E 1.44269504f
#define ONE2 0x3C003C00u

// pitch: 64 elems * 2B + 16B pad = 144 bytes (conflict-free ldmatrix)
#define PITCH 144
#define QTB (128 * PITCH)     // 18432 (Q tile: 128 rows)
#define KTB (64 * PITCH)      // 9216  (K/V tile: 64 rows)
#define OFF_QH 0
#define OFF_QL (OFF_QH + QTB)
#define OFF_KV(buf) (2 * QTB + (buf) * 2 * KTB)
#define SMEM_BYTES (2 * QTB + 2 * 2 * KTB)   // 73728

// ---------------- scratch (fp16, repacked [b,h,s,e]) ----------------
__device__ __half g_Qh[(size_t)Bn * Hn * Ln * En];
__device__ __half g_Ql[(size_t)Bn * Hn * Ln * En];
__device__ __half g_Kf[(size_t)Bn * Hn * Sn * En];
__device__ __half g_Vf[(size_t)Bn * Hn * Sn * Dn];

// ---------------- helpers ----------------
__device__ __forceinline__ u32 smem_u32(const void* p) {
    u32 a;
    asm("{ .reg .u64 t; cvta.to.shared.u64 t, %1; cvt.u32.u64 %0, t; }" : "=r"(a) : "l"(p));
    return a;
}
__device__ __forceinline__ void cpa16(u32 dst, const void* src) {
    asm volatile("cp.async.cg.shared.global [%0], [%1], 16;" :: "r"(dst), "l"(src));
}
__device__ __forceinline__ void cpa_commit() {
    asm volatile("cp.async.commit_group;" ::: "memory");
}
template <int N>
__device__ __forceinline__ void cpa_wait() {
    asm volatile("cp.async.wait_group %0;" :: "n"(N) : "memory");
}
__device__ __forceinline__ void ldsm_x4(u32* r, u32 addr) {
    asm volatile("ldmatrix.sync.aligned.m8n8.x4.shared.b16 {%0,%1,%2,%3}, [%4];"
                 : "=r"(r[0]), "=r"(r[1]), "=r"(r[2]), "=r"(r[3]) : "r"(addr));
}
__device__ __forceinline__ void ldsm_x4_t(u32* r, u32 addr) {
    asm volatile("ldmatrix.sync.aligned.m8n8.x4.trans.shared.b16 {%0,%1,%2,%3}, [%4];"
                 : "=r"(r[0]), "=r"(r[1]), "=r"(r[2]), "=r"(r[3]) : "r"(addr));
}
__device__ __forceinline__ void mma_fp16(float* c, const u32* a, u32 b0, u32 b1) {
    asm volatile(
        "mma.sync.aligned.m16n8k16.row.col.f32.f16.f16.f32 "
        "{%0,%1,%2,%3}, {%4,%5,%6,%7}, {%8,%9}, {%0,%1,%2,%3};"
        : "+f"(c[0]), "+f"(c[1]), "+f"(c[2]), "+f"(c[3])
        : "r"(a[0]), "r"(a[1]), "r"(a[2]), "r"(a[3]), "r"(b0), "r"(b1));
}
__device__ __forceinline__ u32 cvt_f16x2(float lo, float hi) {
    u32 d;
    asm("cvt.rn.f16x2.f32 %0, %1, %2;" : "=r"(d) : "f"(hi), "f"(lo));
    return d;
}
__device__ __forceinline__ u32 ex2_f16x2(u32 x) {
    u32 d;
    asm("ex2.approx.f16x2 %0, %1;" : "=r"(d) : "r"(x));
    return d;
}
__device__ __forceinline__ u32 hmax2(u32 a, u32 b) {
    u32 d;
    asm("max.f16x2 %0, %1, %2;" : "=r"(d) : "r"(a), "r"(b));
    return d;
}
__device__ __forceinline__ void h2_to_f32(u32 p, float& lo, float& hi) {
    __half2 h = *(__half2*)&p;
    lo = __low2float(h);
    hi = __high2float(h);
}

// ---------------- fused pre-pass: one kernel, 3 regions ----------------
__global__ void pack_all(const float* __restrict__ Q, const float* __restrict__ K,
                         const float* __restrict__ V) {
    const int region = blockIdx.y;
    const int i4 = blockIdx.x * 256 + threadIdx.x;
    const size_t lin = (size_t)i4 * 4;
    const int e = lin & 63;
    const int h = (lin >> 6) & 15;
    const int x = (lin >> 10) & 2047;
    const int b = (int)(lin >> 21);
    const size_t dst = ((((size_t)b * Hn + h) * Ln + x) * En) + e;

    if (region == 0) {
        float4 v = ((const float4*)Q)[i4];
        float xx[4] = {v.x, v.y, v.z, v.w};
        __half hh[4], ll[4];
#pragma unroll
        for (int j = 0; j < 4; ++j) {
            hh[j] = __float2half_rn(xx[j]);
            ll[j] = __float2half_rn(xx[j] - __half2float(hh[j]));
        }
        *(uint2*)(g_Qh + dst) = *(uint2*)hh;
        *(uint2*)(g_Ql + dst) = *(uint2*)ll;
    } else {
        const float* src = (region == 1) ? K : V;
        __half* out = (region == 1) ? g_Kf : g_Vf;
        float4 v = ((const float4*)src)[i4];
        __half hh[4] = {__float2half_rn(v.x), __float2half_rn(v.y),
                        __float2half_rn(v.z), __float2half_rn(v.w)};
        *(uint2*)(out + dst) = *(uint2*)hh;
    }
}

// ---------------- main attention kernel ----------------
extern __shared__ char dsm[];

__global__ __launch_bounds__(NT, 2)
void fattn_mma(float* __restrict__ O) {
    const u32 sb = smem_u32(dsm);
    const int tid = threadIdx.x;
    const int w = tid >> 5;
    const int lane = tid & 31;

    const int bh = blockIdx.y;
    const int b = bh >> 4, h = bh & 15;
    const int mbase = blockIdx.x * BM;

    const __half* gq_h = g_Qh + ((size_t)bh * Ln + mbase) * En;
    const __half* gq_l = g_Ql + ((size_t)bh * Ln + mbase) * En;
    const __half* gk   = g_Kf + (size_t)bh * Sn * En;
    const __half* gv   = g_Vf + (size_t)bh * Sn * Dn;

    // prologue: Q (128 rows hi/lo) + tile0 K,V
#pragma unroll
    for (int i = 0; i < 4; ++i) {
        int idx = tid + i * NT;
        u32 d = sb + (idx >> 3) * PITCH + (idx & 7) * 16;
        cpa16(d + OFF_QH, (const char*)gq_h + idx * 16);
        cpa16(d + OFF_QL, (const char*)gq_l + idx * 16);
    }
#pragma unroll
    for (int i = 0; i < 2; ++i) {
        int idx = tid + i * NT;
        u32 d = sb + OFF_KV(0) + (idx >> 3) * PITCH + (idx & 7) * 16;
        cpa16(d + 0 * KTB, (const char*)gk + idx * 16);
        cpa16(d + 1 * KTB, (const char*)gv + idx * 16);
    }
    cpa_commit();

    const u32 koff = (lane & 7) * PITCH + (lane >> 3) * 16;
    const u32 qoff = (16 * w + ((lane >> 3) & 1) * 8 + (lane & 7)) * PITCH + (lane >> 4) * 16;
    const u32 voff = (((lane >> 3) & 1) * 8 + (lane & 7)) * PITCH + (lane >> 4) * 16;

    u32 Qh[4][4], Ql[4][4];            // persistent (tile-invariant)
    float accO[8][4];
#pragma unroll
    for (int j = 0; j < 8; ++j)
#pragma unroll
        for (int i = 0; i < 4; ++i) accO[j][i] = 0.f;
    float accL[4] = {0.f, 0.f, 0.f, 0.f};
    float m0 = -1e30f, m1 = -1e30f;

    for (int t = 0; t < NTILES; ++t) {
        const u32 kvb = sb + OFF_KV(t & 1);

        cpa_wait<0>();
        __syncthreads();      // data visible + prev buffer free

        if (t + 1 < NTILES) {
            const u32 nb = sb + OFF_KV((t + 1) & 1);
            const size_t goffK = (size_t)(t + 1) * BN * En;
            const size_t goffV = (size_t)(t + 1) * BN * Dn;
#pragma unroll
            for (int i = 0; i < 2; ++i) {
                int idx = tid + i * NT;
                u32 d = nb + (idx >> 3) * PITCH + (idx & 7) * 16;
                cpa16(d + 0 * KTB, (const char*)(gk + goffK) + idx * 16);
                cpa16(d + 1 * KTB, (const char*)(gv + goffV) + idx * 16);
            }
            cpa_commit();
        }

        if (t == 0) {
#pragma unroll
            for (int k = 0; k < 4; ++k) {
                ldsm_x4(Qh[k], sb + OFF_QH + k * 32 + qoff);
                ldsm_x4(Ql[k], sb + OFF_QL + k * 32 + qoff);
            }
        }

        // ---- S = Qh*K + Ql*K (fp16 2-term), software-pipelined K fragments ----
        float accS[8][4];
#pragma unroll
        for (int j = 0; j < 8; ++j)
#pragma unroll
            for (int i = 0; i < 4; ++i) accS[j][i] = 0.f;

        {
            const u32 kbase = kvb + koff;
            u32 kc[4], kn[4];
            ldsm_x4(kc, kbase);
#pragma unroll
            for (int idx = 0; idx < 16; ++idx) {
                const int hh = idx >> 3, j = idx & 7;
                if (idx < 15) {
                    const int n = idx + 1;
                    ldsm_x4(kn, kbase + (n & 7) * (8 * PITCH) + (n >> 3) * 64);
                }
                mma_fp16(accS[j], Qh[2 * hh],     kc[0], kc[1]);
                mma_fp16(accS[j], Ql[2 * hh],     kc[0], kc[1]);
                mma_fp16(accS[j], Qh[2 * hh + 1], kc[2], kc[3]);
                mma_fp16(accS[j], Ql[2 * hh + 1], kc[2], kc[3]);
                kc[0] = kn[0]; kc[1] = kn[1]; kc[2] = kn[2]; kc[3] = kn[3];
            }
        }

        // ---- online softmax: tile row max (packed f16x2 reduce), rescale ----
        float tm0 = fmaxf(accS[0][0], accS[0][1]), tm1 = fmaxf(accS[0][2], accS[0][3]);
#pragma unroll
        for (int j = 1; j < 8; ++j) {
            tm0 = fmaxf(tm0, fmaxf(accS[j][0], accS[j][1]));
            tm1 = fmaxf(tm1, fmaxf(accS[j][2], accS[j][3]));
        }
        // 2 packed shuffles instead of 4 scalar ones; fp16 rounding of the shift
        // is harmless (numerator and denominator share it; range slack ~11)
        u32 tmp = cvt_f16x2(tm0, tm1);
        tmp = hmax2(tmp, __shfl_xor_sync(0xffffffffu, tmp, 1));
        tmp = hmax2(tmp, __shfl_xor_sync(0xffffffffu, tmp, 2));
        h2_to_f32(tmp, tm0, tm1);

        const u32 vbase = kvb + 1 * KTB + voff;
        u32 vc[4], vn[4];
        ldsm_x4_t(vc, vbase);    // first V fragment: overlaps the ALU below

        const float nm0 = fmaxf(m0, tm0);
        const float nm1 = fmaxf(m1, tm1);
        const bool newmax = (nm0 > m0) | (nm1 > m1);
        if (__any_sync(0xffffffffu, newmax)) {
            const float al0 = __expf(m0 - nm0);
            const float al1 = __expf(m1 - nm1);
#pragma unroll
            for (int j = 0; j < 8; ++j) {
                accO[j][0] *= al0; accO[j][1] *= al0;
                accO[j][2] *= al1; accO[j][3] *= al1;
            }
            accL[0] *= al0;
            accL[2] *= al1;
            m0 = nm0; m1 = nm1;
        }
        const float c0 = -m0 * L2E;
        const float c1 = -m1 * L2E;

        // ---- PV: per kt convert to fp16 P, then MMAs with pipelined V fragments ----
#pragma unroll
        for (int idx = 0; idx < 16; ++idx) {
            const int kt = idx >> 2, q = idx & 3;
            u32 ah[4];
            if (q == 0) {
                ah[0] = ex2_f16x2(cvt_f16x2(fmaf(accS[2 * kt][0], L2E, c0),
                                            fmaf(accS[2 * kt][1], L2E, c0)));
                ah[1] = ex2_f16x2(cvt_f16x2(fmaf(accS[2 * kt][2], L2E, c1),
                                            fmaf(accS[2 * kt][3], L2E, c1)));
                ah[2] = ex2_f16x2(cvt_f16x2(fmaf(accS[2 * kt + 1][0], L2E, c0),
                                            fmaf(accS[2 * kt + 1][1], L2E, c0)));
                ah[3] = ex2_f16x2(cvt_f16x2(fmaf(accS[2 * kt + 1][2], L2E, c1),
                                            fmaf(accS[2 * kt + 1][3], L2E, c1)));
                // stash in accS slots (dead after conversion) so ah persists across q
                accS[2 * kt][0] = __uint_as_float(ah[0]);
                accS[2 * kt][1] = __uint_as_float(ah[1]);
                accS[2 * kt][2] = __uint_as_float(ah[2]);
                accS[2 * kt][3] = __uint_as_float(ah[3]);
                mma_fp16(accL, ah, ONE2, ONE2);   // row sums via tensor pipe
            } else {
                ah[0] = __float_as_uint(accS[2 * kt][0]);
                ah[1] = __float_as_uint(accS[2 * kt][1]);
                ah[2] = __float_as_uint(accS[2 * kt][2]);
                ah[3] = __float_as_uint(accS[2 * kt][3]);
            }
            if (idx < 15) {
                const int n = idx + 1;
                ldsm_x4_t(vn, vbase + (n >> 2) * (16 * PITCH) + (n & 3) * 32);
            }
            mma_fp16(accO[2 * q],     ah, vc[0], vc[1]);
            mma_fp16(accO[2 * q + 1], ah, vc[2], vc[3]);
            vc[0] = vn[0]; vc[1] = vn[1]; vc[2] = vn[2]; vc[3] = vn[3];
        }
    }

    // ---- epilogue: l exact from the ones-MMA ----
    const float inv0 = 1.f / accL[0];
    const float inv1 = 1.f / accL[2];

    const int row0 = mbase + 16 * w + (lane >> 2);
    float* o0 = O + (((size_t)b * Ln + row0) * Hn + h) * Dn + (lane & 3) * 2;
    float* o1 = o0 + (size_t)8 * Hn * Dn;
#pragma unroll
    for (int j = 0; j < 8; ++j) {
        *(float2*)(o0 + 8 * j) = make_float2(accO[j][0] * inv0, accO[j][1] * inv0);
        *(float2*)(o1 + 8 * j) = make_float2(accO[j][2] * inv1, accO[j][3] * inv1);
    }
}

// ---------------- launch ----------------
extern "C" void kernel_launch(void* const* d_in, const int* in_sizes, int n_in,
                              void* d_out, int out_size) {
    const float* Q = (const float*)d_in[0];
    const float* K = (const float*)d_in[1];
    const float* V = (const float*)d_in[2];
    float* O = (float*)d_out;

    pack_all<<<dim3(8192, 3), 256>>>(Q, K, V);

    cudaFuncSetAttribute(fattn_mma, cudaFuncAttributeMaxDynamicSharedMemorySize, SMEM_BYTES);
    fattn_mma<<<dim3(Ln / BM, Bn * Hn), NT, SMEM_BYTES>>>(O);
}